// round 9
// baseline (speedup 1.0000x reference)
#include <cuda_runtime.h>
#include <cooperative_groups.h>
#include <math.h>

namespace cg = cooperative_groups;

#define ROW_LEN   65536
#define CSIZE     8
#define SEG       (ROW_LEN / CSIZE)     // 8192 elements per CTA
#define THREADS   256
#define TPT       32                    // thread owns [e0, e0+32)
#define JOFF      8

#define TREND_SCALING       0.6f
#define DETAIL_PRESERVATION 0.85f
#define SPIKE_THRESHOLD     3.5f
#define SPIKE_DAMPING       0.35f
#define EPS_STD             1e-6f
#define F_KEEP   DETAIL_PRESERVATION                      // 0.85
#define F_DAMP   (DETAIL_PRESERVATION * SPIKE_DAMPING)    // 0.2975
#define C5       ((1.0f - TREND_SCALING) * 0.2f)          // 0.08
#define C11      (TREND_SCALING / 11.0f)

// XOR swizzle: permutes 16B quads within 128B rows; per-lane stride of 32
// floats makes every float4 LDS/STS bank-conflict-free.
__device__ __forceinline__ int SX(int j) { return j ^ ((j >> 3) & 0x1C); }

// smem layout (floats): data cells j in [0, 8208), then scratch
#define OFF_RED     8224                // 17 floats: warp partials + thr
#define OFF_MAIL    8244                // 16 floats: per-rank (s, ss)
#define SMEM_FLOATS 8260
#define SMEM_BYTES  (SMEM_FLOATS * 4)

__device__ __forceinline__ float4 LD4(const float* sm, int j) {
    return *reinterpret_cast<const float4*>(sm + SX(j));
}
__device__ __forceinline__ void ST4(float* sm, int j, float4 v) {
    *reinterpret_cast<float4*>(sm + SX(j)) = v;
}

// reflect over the full row [0, ROW_LEN)
__device__ __forceinline__ int rrow(int g) {
    if (g < 0) g = -g;
    if (g >= ROW_LEN) g = 2 * ROW_LEN - 2 - g;
    return g;
}

// cluster-wide threshold from per-thread (s, ss). Deterministic order.
__device__ __forceinline__ float cluster_threshold(
    cg::cluster_group& cl, float s, float ss, float* sm, int rank, int tid)
{
    float* red  = sm + OFF_RED;
    float* mail = sm + OFF_MAIL;
    const unsigned m = 0xffffffffu;
    #pragma unroll
    for (int off = 16; off; off >>= 1) {
        s  += __shfl_down_sync(m, s,  off);
        ss += __shfl_down_sync(m, ss, off);
    }
    const int wid = tid >> 5, lid = tid & 31;
    if (lid == 0) { red[wid] = s; red[8 + wid] = ss; }
    __syncthreads();
    if (tid == 0) {
        float bs = 0.f, bss = 0.f;
        #pragma unroll
        for (int w = 0; w < 8; w++) { bs += red[w]; bss += red[8 + w]; }
        #pragma unroll
        for (int r2 = 0; r2 < CSIZE; r2++) {
            float* pm = cl.map_shared_rank(sm, r2) + OFF_MAIL;
            pm[2 * rank]     = bs;
            pm[2 * rank + 1] = bss;
        }
    }
    cl.sync();
    if (tid == 0) {
        float cs = 0.f, css = 0.f;
        #pragma unroll
        for (int r2 = 0; r2 < CSIZE; r2++) {
            cs  += mail[2 * r2];
            css += mail[2 * r2 + 1];
        }
        const float n = (float)ROW_LEN;
        float var = (css - cs * cs / n) / (n - 1.0f);
        var = fmaxf(var, 0.0f);
        red[16] = fmaxf(sqrtf(var), EPS_STD) * SPIKE_THRESHOLD;
    }
    __syncthreads();
    return red[16];
}

// one damped output element
#define EMIT(dst, cur)                                             \
    do {                                                           \
        float _r = (cur) - 0.2f * s5;                              \
        float _f = (fabsf(_r) > thr) ? F_DAMP : F_KEEP;            \
        float _c = fmaf(s5, C5, s11 * C11);                        \
        dst = fmaf(_r, _f, _c);                                    \
    } while (0)

__global__ void __launch_bounds__(THREADS, 4) __cluster_dims__(CSIZE, 1, 1)
fd9_kernel(const float* __restrict__ x, float* __restrict__ out)
{
    extern __shared__ float sm[];
    cg::cluster_group cl = cg::this_cluster();
    const int rank = (int)cl.block_rank();
    const int row  = blockIdx.x / CSIZE;
    const int tid  = threadIdx.x;
    const int lane = tid & 31;
    const float* xr = x + (size_t)row * ROW_LEN;
    const int e0   = rank * SEG + tid * TPT;   // row-local element 0 of thread
    const int base = JOFF + tid * TPT;         // smem cell of element 0

    // ================= phase 1: stage x + stats1 from the load stream =======
    float s1 = 0.f, ss1 = 0.f;
    {
        float v[TPT];
        #pragma unroll
        for (int i = 0; i < 8; i++) {
            float4 t = *reinterpret_cast<const float4*>(xr + e0 + 4 * i);
            ST4(sm, base + 4 * i, t);
            v[4 * i + 0] = t.x; v[4 * i + 1] = t.y;
            v[4 * i + 2] = t.z; v[4 * i + 3] = t.w;
        }
        const unsigned m = 0xffffffffu;
        float hm2 = __shfl_up_sync(m, v[30], 1);
        float hm1 = __shfl_up_sync(m, v[31], 1);
        float h32 = __shfl_down_sync(m, v[0], 1);
        float h33 = __shfl_down_sync(m, v[1], 1);
        if (lane == 0)  { hm2 = xr[rrow(e0 - 2)];  hm1 = xr[rrow(e0 - 1)]; }
        if (lane == 31) { h32 = xr[rrow(e0 + 32)]; h33 = xr[rrow(e0 + 33)]; }

        #define W(i) ((i) < 0 ? ((i) == -2 ? hm2 : hm1)                    \
                             : ((i) > 31 ? ((i) == 32 ? h32 : h33) : v[(i)]))
        float s5 = hm2 + hm1 + v[0] + v[1] + v[2];
        #pragma unroll
        for (int o = 0; o < TPT; o++) {
            if (o) s5 += W(o + 2) - W(o - 3);
            float r = v[o] - 0.2f * s5;
            s1 += r;  ss1 += r * r;
        }
        #undef W
    }
    const float thr1 = cluster_threshold(cl, s1, ss1, sm, rank, tid);
    // (cl.sync inside also made every CTA's staged x visible cluster-wide)

    // ================= phase 2: update1 (in-place) + interior stats2 ========
    float s2 = 0.f, ss2 = 0.f;
    {
        const float thr = thr1;
        float4 lm, l, r6, r7;
        if (tid == 0) {
            lm = make_float4(xr[rrow(e0-8)], xr[rrow(e0-7)], xr[rrow(e0-6)], xr[rrow(e0-5)]);
            l  = make_float4(xr[rrow(e0-4)], xr[rrow(e0-3)], xr[rrow(e0-2)], xr[rrow(e0-1)]);
        } else {
            lm = LD4(sm, base - 8);
            l  = LD4(sm, base - 4);
        }
        if (tid == THREADS - 1) {
            r6 = make_float4(xr[rrow(e0+32)], xr[rrow(e0+33)], xr[rrow(e0+34)], xr[rrow(e0+35)]);
            r7 = make_float4(xr[rrow(e0+36)], xr[rrow(e0+37)], xr[rrow(e0+38)], xr[rrow(e0+39)]);
        } else {
            r6 = LD4(sm, base + 32);
            r7 = LD4(sm, base + 36);
        }
        __syncthreads();   // all old-x reads complete before any o store

        float4 a = LD4(sm, base);
        float4 b = LD4(sm, base + 4);
        float4 qm1 = l;
        float  em5 = lm.w;
        float  s5  = l.z + l.w + a.x + a.y + a.z;
        float  s11 = em5 + l.x + l.y + l.z + l.w +
                     a.x + a.y + a.z + a.w + b.x + b.y;
        float4 po;  float ppw = 0.f;

        #pragma unroll
        for (int k = 0; k < 8; k++) {
            float4 n = (k < 6) ? LD4(sm, base + 4 * k + 8)
                               : ((k == 6) ? r6 : r7);
            float4 o4;
            EMIT(o4.x, a.x);  s5 += a.w - qm1.z;  s11 += b.z - em5;
            EMIT(o4.y, a.y);  s5 += b.x - qm1.w;  s11 += b.w - qm1.x;
            EMIT(o4.z, a.z);  s5 += b.y - a.x;    s11 += n.x - qm1.y;
            EMIT(o4.w, a.w);  s5 += b.z - a.y;    s11 += n.y - qm1.z;
            ST4(sm, base + 4 * k, o4);

            // interior stats2 over o (centers 4k-3 .. 4k, k>=1; skip center 1)
            if (k >= 1) {
                float r2;
                if (k >= 2) {
                    r2 = po.y - 0.2f * (ppw + po.x + po.y + po.z + po.w);
                    s2 += r2; ss2 += r2 * r2;
                }
                r2 = po.z - 0.2f * (po.x + po.y + po.z + po.w + o4.x);
                s2 += r2; ss2 += r2 * r2;
                r2 = po.w - 0.2f * (po.y + po.z + po.w + o4.x + o4.y);
                s2 += r2; ss2 += r2 * r2;
                r2 = o4.x - 0.2f * (po.z + po.w + o4.x + o4.y + o4.z);
                s2 += r2; ss2 += r2 * r2;
            }
            ppw = po.w;
            po  = o4;
            em5 = qm1.w; qm1 = a; a = b; b = n;
        }
        // center 29
        {
            float r2 = po.y - 0.2f * (ppw + po.x + po.y + po.z + po.w);
            s2 += r2; ss2 += r2 * r2;
        }

        // ---- o-halo publish (edge threads only) ----
        if (tid == 0) {
            float4 q0 = LD4(sm, base), q1 = LD4(sm, base + 4);   // own o[0..7]
            if (rank > 0) {
                float* peer = cl.map_shared_rank(sm, rank - 1);
                peer[SX(JOFF + SEG + 0)] = q0.x;
                peer[SX(JOFF + SEG + 1)] = q0.y;
                peer[SX(JOFF + SEG + 2)] = q0.z;
                peer[SX(JOFF + SEG + 3)] = q0.w;
                peer[SX(JOFF + SEG + 4)] = q1.x;
            } else {    // reflect: e[-d] = o[d]
                sm[SX(JOFF - 1)] = q0.y;
                sm[SX(JOFF - 2)] = q0.z;
                sm[SX(JOFF - 3)] = q0.w;
                sm[SX(JOFF - 4)] = q1.x;
                sm[SX(JOFF - 5)] = q1.y;
            }
        }
        if (tid == THREADS - 1) {
            float4 q6 = LD4(sm, base + 24), q7 = LD4(sm, base + 28); // o[24..31]
            if (rank < CSIZE - 1) {
                float* peer = cl.map_shared_rank(sm, rank + 1);
                peer[SX(JOFF - 5)] = q6.w;
                peer[SX(JOFF - 4)] = q7.x;
                peer[SX(JOFF - 3)] = q7.y;
                peer[SX(JOFF - 2)] = q7.z;
                peer[SX(JOFF - 1)] = q7.w;
            } else {    // reflect: e[SEG+k] = o[SEG-2-k]
                sm[SX(JOFF + SEG + 0)] = q7.z;
                sm[SX(JOFF + SEG + 1)] = q7.y;
                sm[SX(JOFF + SEG + 2)] = q7.x;
                sm[SX(JOFF + SEG + 3)] = q6.w;
                sm[SX(JOFF + SEG + 4)] = q6.z;
            }
        }
    }
    cl.sync();   // all o stores + halo publishes visible cluster-wide

    // ================= phase 3: boundary stats2 fixup =======================
    {
        float4 A = LD4(sm, base - 4);    // e[-4..-1]
        float4 B = LD4(sm, base);        // o[0..3]
        float4 C = LD4(sm, base + 28);   // o[28..31]
        float4 D = LD4(sm, base + 32);   // e[32..35]
        float r2;
        r2 = B.x - 0.2f * (A.z + A.w + B.x + B.y + B.z); s2 += r2; ss2 += r2 * r2;
        r2 = B.y - 0.2f * (A.w + B.x + B.y + B.z + B.w); s2 += r2; ss2 += r2 * r2;
        r2 = C.z - 0.2f * (C.x + C.y + C.z + C.w + D.x); s2 += r2; ss2 += r2 * r2;
        r2 = C.w - 0.2f * (C.y + C.z + C.w + D.x + D.y); s2 += r2; ss2 += r2 * r2;
    }
    const float thr2 = cluster_threshold(cl, s2, ss2, sm, rank, tid);

    // ================= phase 4: update2 -> global ===========================
    {
        const float thr = thr2;
        float4 lm = LD4(sm, base - 8);   // only .w (= e[-5]) meaningful
        float4 l  = LD4(sm, base - 4);
        float4 a  = LD4(sm, base);
        float4 b  = LD4(sm, base + 4);
        float4 qm1 = l;
        float  em5 = lm.w;
        float  s5  = l.z + l.w + a.x + a.y + a.z;
        float  s11 = em5 + l.x + l.y + l.z + l.w +
                     a.x + a.y + a.z + a.w + b.x + b.y;

        float4* go = reinterpret_cast<float4*>(out + (size_t)row * ROW_LEN + e0);
        #pragma unroll
        for (int k = 0; k < 8; k++) {
            float4 n = LD4(sm, base + 4 * k + 8);
            float4 o4;
            EMIT(o4.x, a.x);  s5 += a.w - qm1.z;  s11 += b.z - em5;
            EMIT(o4.y, a.y);  s5 += b.x - qm1.w;  s11 += b.w - qm1.x;
            EMIT(o4.z, a.z);  s5 += b.y - a.x;    s11 += n.x - qm1.y;
            EMIT(o4.w, a.w);  s5 += b.z - a.y;    s11 += n.y - qm1.z;
            go[k] = o4;
            em5 = qm1.w; qm1 = a; a = b; b = n;
        }
    }
    // no cross-CTA SMEM access after the cl.sync inside cluster_threshold(thr2)
    // except none -> safe to exit without a trailing cluster barrier.
}

extern "C" void kernel_launch(void* const* d_in, const int* in_sizes, int n_in,
                              void* d_out, int out_size)
{
    const float* x = (const float*)d_in[0];
    float* out = (float*)d_out;
    const int rows = in_sizes[0] / ROW_LEN;   // 512

    cudaFuncSetAttribute(fd9_kernel,
                         cudaFuncAttributeMaxDynamicSharedMemorySize, SMEM_BYTES);
    fd9_kernel<<<rows * CSIZE, THREADS, SMEM_BYTES>>>(x, out);
}